// round 1
// baseline (speedup 1.0000x reference)
#include <cuda_runtime.h>

// LocallyConnectedLinear: out[b,h,w,o] = sum_k xpatch[b,h,w,k] * W[h,w,k,o]
// x:  [8, 32, 32, 64]  f32   (NHWC)
// W:  [30, 30, 576, 64] f32  (k = c*9 + kh*3 + kw ; C slowest)
// out:[8, 30, 30, 64]  f32
//
// HBM-bound on the 132.7 MB weight stream. One CTA per spatial location:
// stage the 8x576 patch in smem, stream weights once as float4.

#define H_OUT 30
#define W_OUT 30
#define H_IN  32
#define W_IN  32
#define C_IN  64
#define C_OUT 64
#define KK    576   // 64 * 3 * 3
#define BATCH 8
#define NTHREADS 128

__global__ __launch_bounds__(NTHREADS, 6)
void lc_kernel(const float* __restrict__ x,
               const float* __restrict__ w,
               float* __restrict__ out)
{
    __shared__ float xs[BATCH][KK];

    const int loc = blockIdx.x;          // 0..899
    const int h   = loc / W_OUT;
    const int wo  = loc - h * W_OUT;
    const int tid = threadIdx.x;

    // ---- Stage im2col patch: xs[b][k], k = c*9 + kh*3 + kw ----
    // 8*576 = 4608 floats -> 36 loads/thread. x lives in L2 (2 MB total).
    #pragma unroll
    for (int idx = tid; idx < BATCH * KK; idx += NTHREADS) {
        const int b  = idx / KK;
        const int k  = idx - b * KK;
        const int c  = k / 9;
        const int r  = k - c * 9;
        const int kh = r / 3;
        const int kw = r - kh * 3;
        xs[b][k] = x[(((b * H_IN) + h + kh) * W_IN + (wo + kw)) * C_IN + c];
    }
    __syncthreads();

    // ---- Main loop: thread = (b, o4). Stream W[h][w] once. ----
    const float4* __restrict__ Wp =
        (const float4*)(w + (size_t)loc * (KK * C_OUT));  // [KK][16] float4
    const int b  = tid >> 4;    // 0..7
    const int o4 = tid & 15;    // 0..15

    const float* __restrict__ xb = xs[b];
    float4 acc = make_float4(0.f, 0.f, 0.f, 0.f);

    #pragma unroll 8
    for (int k = 0; k < KK; ++k) {
        const float4 wv = Wp[k * (C_OUT / 4) + o4];  // LDG.128, coalesced
        const float  xv = xb[k];                     // LDS broadcast in-warp
        acc.x += xv * wv.x;
        acc.y += xv * wv.y;
        acc.z += xv * wv.z;
        acc.w += xv * wv.w;
    }

    float4* __restrict__ op =
        (float4*)(out + ((((size_t)b * H_OUT) + h) * W_OUT + wo) * C_OUT);
    op[o4] = acc;
}

extern "C" void kernel_launch(void* const* d_in, const int* in_sizes, int n_in,
                              void* d_out, int out_size)
{
    const float* x  = (const float*)d_in[0];   // [8,32,32,64]
    const float* w  = (const float*)d_in[1];   // [30,30,576,64]
    float*       o  = (float*)d_out;           // [8,30,30,64]
    (void)in_sizes; (void)n_in; (void)out_size;

    lc_kernel<<<H_OUT * W_OUT, NTHREADS>>>(x, w, o);
}

// round 2
// speedup vs baseline: 1.7221x; 1.7221x over previous
#include <cuda_runtime.h>

// LocallyConnectedLinear: out[b,h,w,o] = sum_k xpatch[b,h,w,k] * W[h,w,k,o]
// x:  [8, 32, 32, 64]  f32   (NHWC)
// W:  [30, 30, 576, 64] f32  (k = c*9 + kh*3 + kw ; C slowest)
// out:[8, 30, 30, 64]  f32
//
// HBM-bound on the 132.7 MB weight stream. One CTA per spatial location.
// R1 lesson: thread=(b,o4) loaded each weight 8x through L1 (L1=65%, DRAM=33%).
// R2: thread=(kslice,o4) loads each weight ONCE, keeps 8 batch accumulators in
// registers, reduces the 8 k-slices through smem at the end.

#define H_OUT 30
#define W_OUT 30
#define H_IN  32
#define W_IN  32
#define C_IN  64
#define C_OUT 64
#define KK    576   // 64 * 3 * 3
#define BATCH 8
#define NTHREADS 128
#define NSLICE 8
#define KPS    72   // KK / NSLICE

__device__ __forceinline__ void fma4(float4& a, float s, const float4& w) {
    a.x += s * w.x; a.y += s * w.y; a.z += s * w.z; a.w += s * w.w;
}

__global__ __launch_bounds__(NTHREADS, 6)
void lc_kernel(const float* __restrict__ x,
               const float* __restrict__ w,
               float* __restrict__ out)
{
    // 4608 floats = 18 KB. Phase 1: xs[k][b] (KK x 8). Phase 2 (aliased):
    // reduction buffer red[slice][o4][b] as float4 with row pad 9 (8*16*9=1152 float4).
    __shared__ float smem[KK * BATCH];

    const int loc = blockIdx.x;          // 0..899
    const int h   = loc / W_OUT;
    const int wo  = loc - h * W_OUT;
    const int tid = threadIdx.x;

    // ---- Stage im2col patch transposed: xs[k][b], k = c*9 + kh*3 + kw ----
    // Iterate with c fastest so x reads are coalesced (64-float runs).
    #pragma unroll
    for (int idx = tid; idx < BATCH * KK; idx += NTHREADS) {
        const int b   = idx / KK;
        const int r   = idx - b * KK;     // r = (kh*3+kw)*64 + c
        const int khw = r >> 6;           // kh*3 + kw
        const int c   = r & 63;
        const int kh  = khw / 3;
        const int kw  = khw - kh * 3;
        const int k   = c * 9 + khw;      // feature index, C slowest
        smem[k * BATCH + b] =
            x[(((b * H_IN) + h + kh) * W_IN + (wo + kw)) * C_IN + c];
    }
    __syncthreads();

    // ---- Main loop: thread = (kslice, o4). Each weight float4 loaded once. ----
    const int o4 = tid & 15;    // 0..15 -> output float4 group
    const int ks = tid >> 4;    // 0..7  -> k slice
    const float4* __restrict__ Wp =
        (const float4*)(w + (size_t)loc * (KK * C_OUT)) + o4;  // [KK][16]

    float4 acc[BATCH];
    #pragma unroll
    for (int b = 0; b < BATCH; ++b) acc[b] = make_float4(0.f, 0.f, 0.f, 0.f);

    const int kbeg = ks * KPS;
    #pragma unroll 4
    for (int k = kbeg; k < kbeg + KPS; ++k) {
        const float4 wv  = Wp[k * (C_OUT / 4)];                 // unique LDG.128
        const float4 xlo = *(const float4*)&smem[k * BATCH];    // LDS.128 bcast
        const float4 xhi = *(const float4*)&smem[k * BATCH + 4];
        fma4(acc[0], xlo.x, wv);
        fma4(acc[1], xlo.y, wv);
        fma4(acc[2], xlo.z, wv);
        fma4(acc[3], xlo.w, wv);
        fma4(acc[4], xhi.x, wv);
        fma4(acc[5], xhi.y, wv);
        fma4(acc[6], xhi.z, wv);
        fma4(acc[7], xhi.w, wv);
    }

    // ---- Reduce 8 k-slices through smem (aliased; pad 9 avoids bank camping) ----
    __syncthreads();   // everyone done reading xs
    float4* red = (float4*)smem;   // [NSLICE][16][9] float4, 1152 <= 1152
    #pragma unroll
    for (int b = 0; b < BATCH; ++b)
        red[(ks * 16 + o4) * 9 + b] = acc[b];
    __syncthreads();

    const int b = tid >> 4;   // 0..7
    float4 s = red[(0 * 16 + o4) * 9 + b];
    #pragma unroll
    for (int sl = 1; sl < NSLICE; ++sl) {
        const float4 p = red[(sl * 16 + o4) * 9 + b];
        s.x += p.x; s.y += p.y; s.z += p.z; s.w += p.w;
    }

    float4* __restrict__ op =
        (float4*)(out + ((((size_t)b * H_OUT) + h) * W_OUT + wo) * C_OUT);
    op[o4] = s;
}

extern "C" void kernel_launch(void* const* d_in, const int* in_sizes, int n_in,
                              void* d_out, int out_size)
{
    const float* x  = (const float*)d_in[0];   // [8,32,32,64]
    const float* w  = (const float*)d_in[1];   // [30,30,576,64]
    float*       o  = (float*)d_out;           // [8,30,30,64]
    (void)in_sizes; (void)n_in; (void)out_size;

    lc_kernel<<<H_OUT * W_OUT, NTHREADS>>>(x, w, o);
}